// round 3
// baseline (speedup 1.0000x reference)
#include <cuda_runtime.h>
#include <cuda_bf16.h>
#include <cstdint>

// Problem constants
#define NRES 768
#define SMSA 512
#define TF   21
#define MSADIM 49
#define CZ   128
#define CM   256
#define MSA_OUT_ELEMS (512u*768u*256u)   // 100663296
#define ROWS_TOTAL (512*768)             // 393216

// ---------------- device scratch ----------------
__device__ float g_tfi[NRES * CZ];
__device__ float g_tfj[NRES * CZ];
__device__ float g_comb[NRES * CM];

// ---------------- helpers ----------------
__device__ __forceinline__ uint32_t smem_u32(const void* p) {
    uint32_t a;
    asm("{ .reg .u64 t; cvta.to.shared.u64 t, %1; cvt.u32.u64 %0, t; }" : "=r"(a) : "l"(p));
    return a;
}

#define LDSM_X4(r, addr) \
    asm volatile("ldmatrix.sync.aligned.m8n8.x4.shared.b16 {%0,%1,%2,%3}, [%4];" \
                 : "=r"((r)[0]), "=r"((r)[1]), "=r"((r)[2]), "=r"((r)[3]) : "r"(addr))
#define LDSM_X4T(r, addr) \
    asm volatile("ldmatrix.sync.aligned.m8n8.x4.trans.shared.b16 {%0,%1,%2,%3}, [%4];" \
                 : "=r"((r)[0]), "=r"((r)[1]), "=r"((r)[2]), "=r"((r)[3]) : "r"(addr))
#define MMA16816(d, a, b0v, b1v) \
    asm volatile("mma.sync.aligned.m16n8k16.row.col.f32.bf16.bf16.f32 " \
                 "{%0,%1,%2,%3}, {%4,%5,%6,%7}, {%8,%9}, {%0,%1,%2,%3};" \
                 : "+f"((d)[0]), "+f"((d)[1]), "+f"((d)[2]), "+f"((d)[3]) \
                 : "r"((a)[0]), "r"((a)[1]), "r"((a)[2]), "r"((a)[3]), \
                   "r"(b0v), "r"(b1v))

// ---------------- kernel 1: tiny precompute ----------------
__global__ void pre_kernel(const float* __restrict__ tf,
                           const float* __restrict__ wzi, const float* __restrict__ bzi,
                           const float* __restrict__ wzj, const float* __restrict__ bzj,
                           const float* __restrict__ wm,  const float* __restrict__ bm,
                           const float* __restrict__ bmsa) {
    __shared__ float t[TF];
    int i = blockIdx.x;
    int c = threadIdx.x;
    if (c < TF) t[c] = tf[i * TF + c];
    __syncthreads();

    float am = bm[c] + bmsa[c];
#pragma unroll
    for (int k = 0; k < TF; k++) am += t[k] * wm[k * CM + c];
    g_comb[i * CM + c] = am;

    if (c < CZ) {
        float ai = bzi[c];
        float aj = bzj[c];
#pragma unroll
        for (int k = 0; k < TF; k++) {
            float tv = t[k];
            ai += tv * wzi[k * CZ + c];
            aj += tv * wzj[k * CZ + c];
        }
        g_tfi[i * CZ + c] = ai;
        g_tfj[i * CZ + c] = aj;
    }
}

// ---------------- kernel 2: MSA GEMM via mma.sync (HMMA, bf16 3-split) ----------------
// CTA: 128 msa rows x 256 channels, K=49 padded to 64. 512 threads = 16 warps.
// Warp = m32 x n64. D = Ah*Bh + Al*Bh + Ah*Bl (fp32 acc) for full fp32 fidelity.
//
// SMEM (dynamic, 104448 B):
//  rows_hi [128][72] bf16, stride 144B      @ 0       (18432)
//  rows_lo                                  @ 18432   (18432)
//  w_hi    [64][264] bf16, stride 528B      @ 36864   (33792)
//  w_lo                                     @ 70656   (33792)
#define R_STRIDE 144
#define W_STRIDE 528
#define OFF_RLO 18432
#define OFF_WHI 36864
#define OFF_WLO 70656
#define MSA_SMEM 104448

__global__ void __launch_bounds__(512, 1) msa_mma_kernel(const float* __restrict__ msa,
                                                         const float* __restrict__ w,
                                                         float* __restrict__ out) {
    extern __shared__ char smem[];
    uint32_t sb = smem_u32(smem);
    int tid = threadIdx.x;
    int lane = tid & 31;
    int warp_m = (tid >> 5) & 3;   // 4 m-warps of 32 rows
    int warp_n = tid >> 7;         // 4 n-warps of 64 channels
    long rowbase = (long)blockIdx.x * 128;
    int n0 = (int)(rowbase % NRES);   // 128 | 768 -> no wrap within CTA

    // ---- zero all smem (covers K/N padding), then fill ----
    {
        uint4* p = (uint4*)smem;
        for (int i = tid; i < MSA_SMEM / 16; i += 512) p[i] = make_uint4(0, 0, 0, 0);
    }
    __syncthreads();

    // rows: 128 x 49 contiguous floats -> hi/lo bf16 at [row][k]
    {
        const float* src = msa + rowbase * (long)MSADIM;
        for (int e = tid; e < 128 * MSADIM; e += 512) {
            int row = e / MSADIM;
            int k = e - row * MSADIM;
            float a = src[e];
            __nv_bfloat16 h = __float2bfloat16(a);
            __nv_bfloat16 l = __float2bfloat16(a - __bfloat162float(h));
            uint32_t o = row * R_STRIDE + k * 2;
            *(__nv_bfloat16*)(smem + o) = h;
            *(__nv_bfloat16*)(smem + OFF_RLO + o) = l;
        }
    }
    // weights: [49][256] row-major (n contiguous) -> [k][n] stride 528B, 4-wide
    {
        const float4* src4 = (const float4*)w;
        for (int g = tid; g < (MSADIM * CM) / 4; g += 512) {
            float4 v = src4[g];
            int e = g * 4;
            int k = e >> 8;
            int n = e & 255;
            __nv_bfloat16 h[4], l[4];
            float vv[4] = {v.x, v.y, v.z, v.w};
#pragma unroll
            for (int i = 0; i < 4; i++) {
                h[i] = __float2bfloat16(vv[i]);
                l[i] = __float2bfloat16(vv[i] - __bfloat162float(h[i]));
            }
            uint32_t o = k * W_STRIDE + n * 2;
            *(uint2*)(smem + OFF_WHI + o) = *(uint2*)h;
            *(uint2*)(smem + OFF_WLO + o) = *(uint2*)l;
        }
    }
    __syncthreads();

    // ---- per-thread ldmatrix base addresses ----
    // A (m16k16, non-trans): lane l -> row (l&15), col-half (l>>4)*16B
    uint32_t aoff = (uint32_t)((warp_m * 32 + (lane & 15)) * R_STRIDE + (lane >> 4) * 16);
    // B (k16n16, trans): lane l -> k row (l&7)+((l>>3)&1)*8, n-half (l>>4)*8
    uint32_t boff = (uint32_t)(((lane & 7) + ((lane >> 3) & 1) * 8) * W_STRIDE +
                               (warp_n * 64 + (lane >> 4) * 8) * 2);
    uint32_t a_hi = sb + aoff;
    uint32_t a_lo = sb + OFF_RLO + aoff;
    uint32_t b_hi = sb + OFF_WHI + boff;
    uint32_t b_lo = sb + OFF_WLO + boff;

    float d[2][8][4];
#pragma unroll
    for (int mt = 0; mt < 2; mt++)
#pragma unroll
        for (int nt = 0; nt < 8; nt++)
#pragma unroll
            for (int i = 0; i < 4; i++) d[mt][nt][i] = 0.0f;

#pragma unroll
    for (int ks = 0; ks < 4; ks++) {
        uint32_t ak = ks * 32;              // k0*2 bytes
        uint32_t bk = ks * 16 * W_STRIDE;

        uint32_t ah[2][4], al[2][4];
        LDSM_X4(ah[0], a_hi + ak);
        LDSM_X4(ah[1], a_hi + 16 * R_STRIDE + ak);
        LDSM_X4(al[0], a_lo + ak);
        LDSM_X4(al[1], a_lo + 16 * R_STRIDE + ak);

        uint32_t bh[4][4];
#pragma unroll
        for (int g = 0; g < 4; g++) LDSM_X4T(bh[g], b_hi + bk + g * 32);

#pragma unroll
        for (int mt = 0; mt < 2; mt++)
#pragma unroll
            for (int nt = 0; nt < 8; nt++) {
                uint32_t b0v = bh[nt >> 1][(nt & 1) * 2];
                uint32_t b1v = bh[nt >> 1][(nt & 1) * 2 + 1];
                MMA16816(d[mt][nt], ah[mt], b0v, b1v);   // Ah*Bh
                MMA16816(d[mt][nt], al[mt], b0v, b1v);   // Al*Bh
            }

        uint32_t bl[4][4];
#pragma unroll
        for (int g = 0; g < 4; g++) LDSM_X4T(bl[g], b_lo + bk + g * 32);

#pragma unroll
        for (int mt = 0; mt < 2; mt++)
#pragma unroll
            for (int nt = 0; nt < 8; nt++) {
                uint32_t b0v = bl[nt >> 1][(nt & 1) * 2];
                uint32_t b1v = bl[nt >> 1][(nt & 1) * 2 + 1];
                MMA16816(d[mt][nt], ah[mt], b0v, b1v);   // Ah*Bl
            }
    }

    // ---- epilogue: add comb, store float2 pairs ----
    int qr = lane >> 2;
    int qc = (lane & 3) * 2;
#pragma unroll
    for (int mt = 0; mt < 2; mt++) {
        int lrow0 = warp_m * 32 + mt * 16 + qr;
#pragma unroll
        for (int nt = 0; nt < 8; nt++) {
            int ch = warp_n * 64 + nt * 8 + qc;
            float2 cb0 = *(const float2*)(g_comb + (n0 + lrow0) * CM + ch);
            float2 cb1 = *(const float2*)(g_comb + (n0 + lrow0 + 8) * CM + ch);
            float2 o0 = make_float2(d[mt][nt][0] + cb0.x, d[mt][nt][1] + cb0.y);
            float2 o1 = make_float2(d[mt][nt][2] + cb1.x, d[mt][nt][3] + cb1.y);
            *(float2*)(out + (rowbase + lrow0) * (long)CM + ch) = o0;
            *(float2*)(out + (rowbase + lrow0 + 8) * (long)CM + ch) = o1;
        }
    }
}

// ---------------- kernel 3: pair embedding ----------------
__global__ void __launch_bounds__(256) pair_kernel(const int* __restrict__ res,
                                                   const int* __restrict__ sym,
                                                   const int* __restrict__ asym,
                                                   const int* __restrict__ ent,
                                                   const float* __restrict__ w_rel,
                                                   const float* __restrict__ b_rel,
                                                   float* __restrict__ pair_out) {
    __shared__ int s_res[NRES];
    __shared__ int s_sym[NRES];
    __shared__ int s_asym[NRES];
    __shared__ float s_base[CZ];

    int tid = threadIdx.x;
    int i = blockIdx.x;

    for (int t = tid; t < NRES; t += 256) {
        s_res[t]  = res[t];
        s_sym[t]  = sym[t];
        s_asym[t] = asym[t];
    }
    if (tid < CZ) s_base[tid] = b_rel[tid] + g_tfi[i * CZ + tid];
    __syncthreads();

    int cq = tid & 31;
    int jl = tid >> 5;

    int res_i  = s_res[i];
    int sym_i  = s_sym[i];
    int asym_i = s_asym[i];
    int ent_i  = ent[i];

    float4 base4 = ((const float4*)s_base)[cq];
    const float4* W4 = (const float4*)w_rel;
    float4 w66 = W4[66 * 32 + cq];

    int jstart = blockIdx.y * 192;
#pragma unroll 4
    for (int it = 0; it < 24; it++) {
        int j = jstart + it * 8 + jl;
        int rj = s_res[j], sj = s_sym[j], aj = s_asym[j];

        int off = res_i - rj + 32;
        off = min(max(off, 0), 64);
        int pos = (asym_i == aj) ? off : 65;

        int ed = ent_i - sj;
        float entf = (float)ed;

        int cc = sym_i - sj + 2;
        cc = min(max(cc, 0), 4);
        int chain = (ed != 0) ? cc : 5;

        float4 wp = W4[pos * 32 + cq];
        float4 wc = W4[(67 + chain) * 32 + cq];
        float4 tj = ((const float4*)(g_tfj + j * CZ))[cq];

        float4 o;
        o.x = base4.x + wp.x + entf * w66.x + wc.x + tj.x;
        o.y = base4.y + wp.y + entf * w66.y + wc.y + tj.y;
        o.z = base4.z + wp.z + entf * w66.z + wc.z + tj.z;
        o.w = base4.w + wp.w + entf * w66.w + wc.w + tj.w;

        ((float4*)(pair_out + ((size_t)i * NRES + j) * CZ))[cq] = o;
    }
}

// ---------------- launch ----------------
extern "C" void kernel_launch(void* const* d_in, const int* in_sizes, int n_in,
                              void* d_out, int out_size) {
    const float* tf     = (const float*)d_in[0];
    const float* msa    = (const float*)d_in[1];
    const int*   res    = (const int*)d_in[2];
    const int*   sym    = (const int*)d_in[3];
    const int*   asym   = (const int*)d_in[4];
    const int*   ent    = (const int*)d_in[5];
    const float* w_zi   = (const float*)d_in[6];
    const float* b_zi   = (const float*)d_in[7];
    const float* w_zj   = (const float*)d_in[8];
    const float* b_zj   = (const float*)d_in[9];
    const float* w_m    = (const float*)d_in[10];
    const float* b_m    = (const float*)d_in[11];
    const float* w_msa  = (const float*)d_in[12];
    const float* b_msa  = (const float*)d_in[13];
    const float* w_rel  = (const float*)d_in[14];
    const float* b_rel  = (const float*)d_in[15];

    float* msa_out  = (float*)d_out;
    float* pair_out = (float*)d_out + MSA_OUT_ELEMS;

    cudaFuncSetAttribute(msa_mma_kernel, cudaFuncAttributeMaxDynamicSharedMemorySize,
                         MSA_SMEM);

    pre_kernel<<<NRES, 256>>>(tf, w_zi, b_zi, w_zj, b_zj, w_m, b_m, b_msa);
    msa_mma_kernel<<<ROWS_TOTAL / 128, 512, MSA_SMEM>>>(msa, w_msa, msa_out);
    pair_kernel<<<dim3(NRES, 4), 256>>>(res, sym, asym, ent, w_rel, b_rel, pair_out);
}

// round 4
// speedup vs baseline: 1.0027x; 1.0027x over previous
#include <cuda_runtime.h>
#include <cuda_bf16.h>
#include <cstdint>

// Problem constants
#define NRES 768
#define SMSA 512
#define TF   21
#define MSADIM 49
#define CZ   128
#define CM   256
#define MSA_OUT_ELEMS (512u*768u*256u)   // 100663296
#define ROWS_TOTAL (512*768)             // 393216

// ---------------- device scratch ----------------
__device__ float g_tfi[NRES * CZ];
__device__ float g_tfj[NRES * CZ];
__device__ float g_comb[NRES * CM];

// ---------------- helpers ----------------
__device__ __forceinline__ uint32_t smem_u32(const void* p) {
    uint32_t a;
    asm("{ .reg .u64 t; cvta.to.shared.u64 t, %1; cvt.u32.u64 %0, t; }" : "=r"(a) : "l"(p));
    return a;
}

#define LDSM_X4(r, addr) \
    asm volatile("ldmatrix.sync.aligned.m8n8.x4.shared.b16 {%0,%1,%2,%3}, [%4];" \
                 : "=r"((r)[0]), "=r"((r)[1]), "=r"((r)[2]), "=r"((r)[3]) : "r"(addr))
#define LDSM_X4T(r, addr) \
    asm volatile("ldmatrix.sync.aligned.m8n8.x4.trans.shared.b16 {%0,%1,%2,%3}, [%4];" \
                 : "=r"((r)[0]), "=r"((r)[1]), "=r"((r)[2]), "=r"((r)[3]) : "r"(addr))
#define MMA16816(d, a, b0v, b1v) \
    asm volatile("mma.sync.aligned.m16n8k16.row.col.f32.bf16.bf16.f32 " \
                 "{%0,%1,%2,%3}, {%4,%5,%6,%7}, {%8,%9}, {%0,%1,%2,%3};" \
                 : "+f"((d)[0]), "+f"((d)[1]), "+f"((d)[2]), "+f"((d)[3]) \
                 : "r"((a)[0]), "r"((a)[1]), "r"((a)[2]), "r"((a)[3]), \
                   "r"(b0v), "r"(b1v))

// ---------------- kernel 1: tiny precompute ----------------
__global__ void pre_kernel(const float* __restrict__ tf,
                           const float* __restrict__ wzi, const float* __restrict__ bzi,
                           const float* __restrict__ wzj, const float* __restrict__ bzj,
                           const float* __restrict__ wm,  const float* __restrict__ bm,
                           const float* __restrict__ bmsa) {
    __shared__ float t[TF];
    int i = blockIdx.x;
    int c = threadIdx.x;
    if (c < TF) t[c] = tf[i * TF + c];
    __syncthreads();

    float am = bm[c] + bmsa[c];
#pragma unroll
    for (int k = 0; k < TF; k++) am += t[k] * wm[k * CM + c];
    g_comb[i * CM + c] = am;

    if (c < CZ) {
        float ai = bzi[c];
        float aj = bzj[c];
#pragma unroll
        for (int k = 0; k < TF; k++) {
            float tv = t[k];
            ai += tv * wzi[k * CZ + c];
            aj += tv * wzj[k * CZ + c];
        }
        g_tfi[i * CZ + c] = ai;
        g_tfj[i * CZ + c] = aj;
    }
}

// ---------------- kernel 2: MSA GEMM via mma.sync (HMMA, bf16 3-split) ----------------
// CTA: 128 msa rows x 256 channels, K=49 padded to 64. 512 threads = 16 warps.
// Warp = m32 x n64. D = Ah*Bh + Al*Bh + Ah*Bl (fp32 acc) for full fp32 fidelity.
//
// SMEM (dynamic, 104448 B):
//  rows_hi [128][72] bf16, stride 144B      @ 0       (18432)
//  rows_lo                                  @ 18432   (18432)
//  w_hi    [64][264] bf16, stride 528B      @ 36864   (33792)
//  w_lo                                     @ 70656   (33792)
#define R_STRIDE 144
#define W_STRIDE 528
#define OFF_RLO 18432
#define OFF_WHI 36864
#define OFF_WLO 70656
#define MSA_SMEM 104448

__global__ void __launch_bounds__(512, 1) msa_mma_kernel(const float* __restrict__ msa,
                                                         const float* __restrict__ w,
                                                         float* __restrict__ out) {
    extern __shared__ char smem[];
    uint32_t sb = smem_u32(smem);
    int tid = threadIdx.x;
    int lane = tid & 31;
    int warp_m = (tid >> 5) & 3;   // 4 m-warps of 32 rows
    int warp_n = tid >> 7;         // 4 n-warps of 64 channels
    long rowbase = (long)blockIdx.x * 128;
    int n0 = (int)(rowbase % NRES);   // 128 | 768 -> no wrap within CTA

    // ---- zero all smem (covers K/N padding), then fill ----
    {
        uint4* p = (uint4*)smem;
        for (int i = tid; i < MSA_SMEM / 16; i += 512) p[i] = make_uint4(0, 0, 0, 0);
    }
    __syncthreads();

    // rows: 128 x 49 contiguous floats -> hi/lo bf16 at [row][k]
    {
        const float* src = msa + rowbase * (long)MSADIM;
        for (int e = tid; e < 128 * MSADIM; e += 512) {
            int row = e / MSADIM;
            int k = e - row * MSADIM;
            float a = src[e];
            __nv_bfloat16 h = __float2bfloat16(a);
            __nv_bfloat16 l = __float2bfloat16(a - __bfloat162float(h));
            uint32_t o = row * R_STRIDE + k * 2;
            *(__nv_bfloat16*)(smem + o) = h;
            *(__nv_bfloat16*)(smem + OFF_RLO + o) = l;
        }
    }
    // weights: [49][256] row-major (n contiguous) -> [k][n] stride 528B, 4-wide
    {
        const float4* src4 = (const float4*)w;
        for (int g = tid; g < (MSADIM * CM) / 4; g += 512) {
            float4 v = src4[g];
            int e = g * 4;
            int k = e >> 8;
            int n = e & 255;
            __nv_bfloat16 h[4], l[4];
            float vv[4] = {v.x, v.y, v.z, v.w};
#pragma unroll
            for (int i = 0; i < 4; i++) {
                h[i] = __float2bfloat16(vv[i]);
                l[i] = __float2bfloat16(vv[i] - __bfloat162float(h[i]));
            }
            uint32_t o = k * W_STRIDE + n * 2;
            *(uint2*)(smem + OFF_WHI + o) = *(uint2*)h;
            *(uint2*)(smem + OFF_WLO + o) = *(uint2*)l;
        }
    }
    __syncthreads();

    // ---- per-thread ldmatrix base addresses ----
    // A (m16k16, non-trans): lane l -> row (l&15), col-half (l>>4)*16B
    uint32_t aoff = (uint32_t)((warp_m * 32 + (lane & 15)) * R_STRIDE + (lane >> 4) * 16);
    // B (k16n16, trans): lane l -> k row (l&7)+((l>>3)&1)*8, n-half (l>>4)*8
    uint32_t boff = (uint32_t)(((lane & 7) + ((lane >> 3) & 1) * 8) * W_STRIDE +
                               (warp_n * 64 + (lane >> 4) * 8) * 2);
    uint32_t a_hi = sb + aoff;
    uint32_t a_lo = sb + OFF_RLO + aoff;
    uint32_t b_hi = sb + OFF_WHI + boff;
    uint32_t b_lo = sb + OFF_WLO + boff;

    float d[2][8][4];
#pragma unroll
    for (int mt = 0; mt < 2; mt++)
#pragma unroll
        for (int nt = 0; nt < 8; nt++)
#pragma unroll
            for (int i = 0; i < 4; i++) d[mt][nt][i] = 0.0f;

#pragma unroll
    for (int ks = 0; ks < 4; ks++) {
        uint32_t ak = ks * 32;              // k0*2 bytes
        uint32_t bk = ks * 16 * W_STRIDE;

        uint32_t ah[2][4], al[2][4];
        LDSM_X4(ah[0], a_hi + ak);
        LDSM_X4(ah[1], a_hi + 16 * R_STRIDE + ak);
        LDSM_X4(al[0], a_lo + ak);
        LDSM_X4(al[1], a_lo + 16 * R_STRIDE + ak);

        uint32_t bh[4][4];
#pragma unroll
        for (int g = 0; g < 4; g++) LDSM_X4T(bh[g], b_hi + bk + g * 32);

#pragma unroll
        for (int mt = 0; mt < 2; mt++)
#pragma unroll
            for (int nt = 0; nt < 8; nt++) {
                uint32_t b0v = bh[nt >> 1][(nt & 1) * 2];
                uint32_t b1v = bh[nt >> 1][(nt & 1) * 2 + 1];
                MMA16816(d[mt][nt], ah[mt], b0v, b1v);   // Ah*Bh
                MMA16816(d[mt][nt], al[mt], b0v, b1v);   // Al*Bh
            }

        uint32_t bl[4][4];
#pragma unroll
        for (int g = 0; g < 4; g++) LDSM_X4T(bl[g], b_lo + bk + g * 32);

#pragma unroll
        for (int mt = 0; mt < 2; mt++)
#pragma unroll
            for (int nt = 0; nt < 8; nt++) {
                uint32_t b0v = bl[nt >> 1][(nt & 1) * 2];
                uint32_t b1v = bl[nt >> 1][(nt & 1) * 2 + 1];
                MMA16816(d[mt][nt], ah[mt], b0v, b1v);   // Ah*Bl
            }
    }

    // ---- epilogue: add comb, store float2 pairs ----
    int qr = lane >> 2;
    int qc = (lane & 3) * 2;
#pragma unroll
    for (int mt = 0; mt < 2; mt++) {
        int lrow0 = warp_m * 32 + mt * 16 + qr;
#pragma unroll
        for (int nt = 0; nt < 8; nt++) {
            int ch = warp_n * 64 + nt * 8 + qc;
            float2 cb0 = *(const float2*)(g_comb + (n0 + lrow0) * CM + ch);
            float2 cb1 = *(const float2*)(g_comb + (n0 + lrow0 + 8) * CM + ch);
            float2 o0 = make_float2(d[mt][nt][0] + cb0.x, d[mt][nt][1] + cb0.y);
            float2 o1 = make_float2(d[mt][nt][2] + cb1.x, d[mt][nt][3] + cb1.y);
            *(float2*)(out + (rowbase + lrow0) * (long)CM + ch) = o0;
            *(float2*)(out + (rowbase + lrow0 + 8) * (long)CM + ch) = o1;
        }
    }
}

// ---------------- kernel 3: pair embedding ----------------
__global__ void __launch_bounds__(256) pair_kernel(const int* __restrict__ res,
                                                   const int* __restrict__ sym,
                                                   const int* __restrict__ asym,
                                                   const int* __restrict__ ent,
                                                   const float* __restrict__ w_rel,
                                                   const float* __restrict__ b_rel,
                                                   float* __restrict__ pair_out) {
    __shared__ int s_res[NRES];
    __shared__ int s_sym[NRES];
    __shared__ int s_asym[NRES];
    __shared__ float s_base[CZ];

    int tid = threadIdx.x;
    int i = blockIdx.x;

    for (int t = tid; t < NRES; t += 256) {
        s_res[t]  = res[t];
        s_sym[t]  = sym[t];
        s_asym[t] = asym[t];
    }
    if (tid < CZ) s_base[tid] = b_rel[tid] + g_tfi[i * CZ + tid];
    __syncthreads();

    int cq = tid & 31;
    int jl = tid >> 5;

    int res_i  = s_res[i];
    int sym_i  = s_sym[i];
    int asym_i = s_asym[i];
    int ent_i  = ent[i];

    float4 base4 = ((const float4*)s_base)[cq];
    const float4* W4 = (const float4*)w_rel;
    float4 w66 = W4[66 * 32 + cq];

    int jstart = blockIdx.y * 192;
#pragma unroll 4
    for (int it = 0; it < 24; it++) {
        int j = jstart + it * 8 + jl;
        int rj = s_res[j], sj = s_sym[j], aj = s_asym[j];

        int off = res_i - rj + 32;
        off = min(max(off, 0), 64);
        int pos = (asym_i == aj) ? off : 65;

        int ed = ent_i - sj;
        float entf = (float)ed;

        int cc = sym_i - sj + 2;
        cc = min(max(cc, 0), 4);
        int chain = (ed != 0) ? cc : 5;

        float4 wp = W4[pos * 32 + cq];
        float4 wc = W4[(67 + chain) * 32 + cq];
        float4 tj = ((const float4*)(g_tfj + j * CZ))[cq];

        float4 o;
        o.x = base4.x + wp.x + entf * w66.x + wc.x + tj.x;
        o.y = base4.y + wp.y + entf * w66.y + wc.y + tj.y;
        o.z = base4.z + wp.z + entf * w66.z + wc.z + tj.z;
        o.w = base4.w + wp.w + entf * w66.w + wc.w + tj.w;

        ((float4*)(pair_out + ((size_t)i * NRES + j) * CZ))[cq] = o;
    }
}

// ---------------- launch ----------------
extern "C" void kernel_launch(void* const* d_in, const int* in_sizes, int n_in,
                              void* d_out, int out_size) {
    const float* tf     = (const float*)d_in[0];
    const float* msa    = (const float*)d_in[1];
    const int*   res    = (const int*)d_in[2];
    const int*   sym    = (const int*)d_in[3];
    const int*   asym   = (const int*)d_in[4];
    const int*   ent    = (const int*)d_in[5];
    const float* w_zi   = (const float*)d_in[6];
    const float* b_zi   = (const float*)d_in[7];
    const float* w_zj   = (const float*)d_in[8];
    const float* b_zj   = (const float*)d_in[9];
    const float* w_m    = (const float*)d_in[10];
    const float* b_m    = (const float*)d_in[11];
    const float* w_msa  = (const float*)d_in[12];
    const float* b_msa  = (const float*)d_in[13];
    const float* w_rel  = (const float*)d_in[14];
    const float* b_rel  = (const float*)d_in[15];

    float* msa_out  = (float*)d_out;
    float* pair_out = (float*)d_out + MSA_OUT_ELEMS;

    cudaFuncSetAttribute(msa_mma_kernel, cudaFuncAttributeMaxDynamicSharedMemorySize,
                         MSA_SMEM);

    pre_kernel<<<NRES, 256>>>(tf, w_zi, b_zi, w_zj, b_zj, w_m, b_m, b_msa);
    msa_mma_kernel<<<ROWS_TOTAL / 128, 512, MSA_SMEM>>>(msa, w_msa, msa_out);
    pair_kernel<<<dim3(NRES, 4), 256>>>(res, sym, asym, ent, w_rel, b_rel, pair_out);
}

// round 5
// speedup vs baseline: 1.5854x; 1.5811x over previous
#include <cuda_runtime.h>
#include <cuda_fp16.h>
#include <cstdint>

// Problem constants
#define NRES 768
#define TF   21
#define MSADIM 49
#define CZ   128
#define CM   256
#define MSA_OUT_ELEMS (512u*768u*256u)   // 100663296
#define NTILES 3072                      // 393216 rows / 128
#define GRID_MSA 148

// ---------------- device scratch ----------------
__device__ float  g_tfi[NRES * CZ];
__device__ float  g_tfj[NRES * CZ];
__device__ float  g_comb[NRES * CM];
__device__ __half g_wh[48 * CM];         // fp16 weights rows k=0..47
__device__ float  g_w48[CM];             // fp32 weight row k=48

// ---------------- smem layout (bytes) ----------------
// A_hi [128][56h] stride 112   @ 0       (14336)
// A_lo                         @ 14336   (14336)
// W    [48][264h] stride 528   @ 28672   (25344)
// raw0 128x49 f32              @ 54016   (25088)
// raw1                         @ 79104   (25088)  -> total 104192
#define A_STRIDE 112
#define W_STRIDE 528
#define OFF_ALO  14336
#define OFF_W    28672
#define OFF_RAW0 54016
#define OFF_RAW1 79104
#define MSA_SMEM 104192

// ---------------- helpers ----------------
__device__ __forceinline__ uint32_t smem_u32(const void* p) {
    uint32_t a;
    asm("{ .reg .u64 t; cvta.to.shared.u64 t, %1; cvt.u32.u64 %0, t; }" : "=r"(a) : "l"(p));
    return a;
}
__device__ __forceinline__ void cp16(uint32_t dst, const void* src) {
    asm volatile("cp.async.cg.shared.global [%0], [%1], 16;" :: "r"(dst), "l"(src) : "memory");
}
__device__ __forceinline__ void cp_commit() {
    asm volatile("cp.async.commit_group;" ::: "memory");
}
__device__ __forceinline__ void cp_wait_all() {
    asm volatile("cp.async.wait_group 0;" ::: "memory");
}

#define LDSM_X4(r, addr) \
    asm volatile("ldmatrix.sync.aligned.m8n8.x4.shared.b16 {%0,%1,%2,%3}, [%4];" \
                 : "=r"((r)[0]), "=r"((r)[1]), "=r"((r)[2]), "=r"((r)[3]) : "r"(addr))
#define LDSM_X4T(r, addr) \
    asm volatile("ldmatrix.sync.aligned.m8n8.x4.trans.shared.b16 {%0,%1,%2,%3}, [%4];" \
                 : "=r"((r)[0]), "=r"((r)[1]), "=r"((r)[2]), "=r"((r)[3]) : "r"(addr))
#define MMAF16(d, a, b0v, b1v) \
    asm volatile("mma.sync.aligned.m16n8k16.row.col.f32.f16.f16.f32 " \
                 "{%0,%1,%2,%3}, {%4,%5,%6,%7}, {%8,%9}, {%0,%1,%2,%3};" \
                 : "+f"((d)[0]), "+f"((d)[1]), "+f"((d)[2]), "+f"((d)[3]) \
                 : "r"((a)[0]), "r"((a)[1]), "r"((a)[2]), "r"((a)[3]), \
                   "r"(b0v), "r"(b1v))

// ---------------- kernel 0: weight conversion ----------------
__global__ void wconv_kernel(const float* __restrict__ w) {
    int k = blockIdx.x;
    int n = threadIdx.x;
    float v = w[k * CM + n];
    if (k < 48) g_wh[k * CM + n] = __float2half_rn(v);
    else        g_w48[n] = v;
}

// ---------------- kernel 1: tiny precompute ----------------
__global__ void pre_kernel(const float* __restrict__ tf,
                           const float* __restrict__ wzi, const float* __restrict__ bzi,
                           const float* __restrict__ wzj, const float* __restrict__ bzj,
                           const float* __restrict__ wm,  const float* __restrict__ bm,
                           const float* __restrict__ bmsa) {
    __shared__ float t[TF];
    int i = blockIdx.x;
    int c = threadIdx.x;
    if (c < TF) t[c] = tf[i * TF + c];
    __syncthreads();

    float am = bm[c] + bmsa[c];
#pragma unroll
    for (int k = 0; k < TF; k++) am += t[k] * wm[k * CM + c];
    g_comb[i * CM + c] = am;

    if (c < CZ) {
        float ai = bzi[c];
        float aj = bzj[c];
#pragma unroll
        for (int k = 0; k < TF; k++) {
            float tv = t[k];
            ai += tv * wzi[k * CZ + c];
            aj += tv * wzj[k * CZ + c];
        }
        g_tfi[i * CZ + c] = ai;
        g_tfj[i * CZ + c] = aj;
    }
}

// ---------------- kernel 2: persistent MSA GEMM (fp16 2-term HMMA) ----------------
// Tile = 128 rows x 256 ch, K=48 via MMA + k=48 scalar fix. 512 thr = 16 warps,
// warp = m32 x n64. D = (Ahi + Alo) * B_fp16, fp32 accum.
__global__ void __launch_bounds__(512, 1) msa_persist_kernel(const float* __restrict__ msa,
                                                             float* __restrict__ out) {
    extern __shared__ char smem[];
    uint32_t sb = smem_u32(smem);
    int tid = threadIdx.x;
    int lane = tid & 31;
    int warp_m = (tid >> 5) & 3;
    int warp_n = tid >> 7;

    // ---- stage weights once (cp.async group shared with first raw prefetch) ----
    for (int g = tid; g < 1536; g += 512) {          // 48 rows x 32 chunks of 16B
        int row = g >> 5;
        int c = g & 31;
        cp16(sb + OFF_W + row * W_STRIDE + c * 16, (const char*)g_wh + row * 512 + c * 16);
    }
    // ---- prefetch first raw tile ----
    int t0 = blockIdx.x;
    {
        const char* src = (const char*)(msa) + (long)t0 * 25088;
        for (int g = tid; g < 1568; g += 512)
            cp16(sb + OFF_RAW0 + g * 16, src + g * 16);
    }
    cp_commit();

    // ldmatrix base offsets
    uint32_t aoff = (uint32_t)((warp_m * 32 + (lane & 15)) * A_STRIDE + (lane >> 4) * 16);
    uint32_t boff = (uint32_t)(((lane & 7) + ((lane >> 3) & 1) * 8) * W_STRIDE +
                               (warp_n * 64 + (lane >> 4) * 8) * 2);
    uint32_t b_base = sb + OFF_W + boff;

    int qr = lane >> 2;
    int qc = (lane & 3) * 2;

    for (int t = t0; t < NTILES; t += GRID_MSA) {
        uint32_t raw_cur = ((t - t0) / GRID_MSA) & 1 ? OFF_RAW1 : OFF_RAW0;
        uint32_t raw_nxt = raw_cur == OFF_RAW0 ? OFF_RAW1 : OFF_RAW0;
        const float* rawf = (const float*)(smem + raw_cur);

        cp_wait_all();
        __syncthreads();   // raw ready; prev MMA/epilogue done -> A reusable

        // ---- convert raw -> A hi/lo fp16 (k<48), half2 stores ----
        for (int g = tid; g < 3072; g += 512) {
            int row = g / 24;
            int p = g - row * 24;
            float a0 = rawf[row * 49 + 2 * p];
            float a1 = rawf[row * 49 + 2 * p + 1];
            __half h0 = __float2half_rn(a0);
            __half h1 = __float2half_rn(a1);
            __half l0 = __float2half_rn(a0 - __half2float(h0));
            __half l1 = __float2half_rn(a1 - __half2float(h1));
            uint32_t o = row * A_STRIDE + p * 4;
            *(__half2*)(smem + o)           = __halves2half2(h0, h1);
            *(__half2*)(smem + OFF_ALO + o) = __halves2half2(l0, l1);
        }
        __syncthreads();   // A ready

        // ---- prefetch next raw (overlaps MMA) ----
        int tn = t + GRID_MSA;
        if (tn < NTILES) {
            const char* src = (const char*)(msa) + (long)tn * 25088;
            for (int g = tid; g < 1568; g += 512)
                cp16(sb + raw_nxt + g * 16, src + g * 16);
        }
        cp_commit();

        // ---- MMA mainloop: 3 k-steps, 2 terms ----
        float d[2][8][4];
#pragma unroll
        for (int mt = 0; mt < 2; mt++)
#pragma unroll
            for (int nt = 0; nt < 8; nt++)
#pragma unroll
                for (int i = 0; i < 4; i++) d[mt][nt][i] = 0.0f;

#pragma unroll
        for (int ks = 0; ks < 3; ks++) {
            uint32_t ak = ks * 32;
            uint32_t bk = ks * 16 * W_STRIDE;

            uint32_t ah[2][4], al[2][4];
            LDSM_X4(ah[0], sb + aoff + ak);
            LDSM_X4(ah[1], sb + aoff + 16 * A_STRIDE + ak);
            LDSM_X4(al[0], sb + OFF_ALO + aoff + ak);
            LDSM_X4(al[1], sb + OFF_ALO + aoff + 16 * A_STRIDE + ak);

            uint32_t bh[4][4];
#pragma unroll
            for (int g = 0; g < 4; g++) LDSM_X4T(bh[g], b_base + bk + g * 32);

#pragma unroll
            for (int mt = 0; mt < 2; mt++)
#pragma unroll
                for (int nt = 0; nt < 8; nt++) {
                    uint32_t b0v = bh[nt >> 1][(nt & 1) * 2];
                    uint32_t b1v = bh[nt >> 1][(nt & 1) * 2 + 1];
                    MMAF16(d[mt][nt], ah[mt], b0v, b1v);
                    MMAF16(d[mt][nt], al[mt], b0v, b1v);
                }
        }

        // ---- epilogue: + a48*w48 + comb, store ----
        long rowbase = (long)t * 128;
        int n0 = (int)(rowbase % NRES);
#pragma unroll
        for (int mt = 0; mt < 2; mt++) {
            int lrow0 = warp_m * 32 + mt * 16 + qr;
            float a48_0 = rawf[lrow0 * 49 + 48];
            float a48_1 = rawf[(lrow0 + 8) * 49 + 48];
#pragma unroll
            for (int nt = 0; nt < 8; nt++) {
                int ch = warp_n * 64 + nt * 8 + qc;
                float2 w48 = *(const float2*)(g_w48 + ch);
                float2 cb0 = *(const float2*)(g_comb + (n0 + lrow0) * CM + ch);
                float2 cb1 = *(const float2*)(g_comb + (n0 + lrow0 + 8) * CM + ch);
                float2 o0 = make_float2(d[mt][nt][0] + a48_0 * w48.x + cb0.x,
                                        d[mt][nt][1] + a48_0 * w48.y + cb0.y);
                float2 o1 = make_float2(d[mt][nt][2] + a48_1 * w48.x + cb1.x,
                                        d[mt][nt][3] + a48_1 * w48.y + cb1.y);
                *(float2*)(out + (rowbase + lrow0) * (long)CM + ch) = o0;
                *(float2*)(out + (rowbase + lrow0 + 8) * (long)CM + ch) = o1;
            }
        }
        __syncthreads();   // rawf(k48) reads done before next convert reuses A...raw
    }
}

// ---------------- kernel 3: pair embedding ----------------
__global__ void __launch_bounds__(256) pair_kernel(const int* __restrict__ res,
                                                   const int* __restrict__ sym,
                                                   const int* __restrict__ asym,
                                                   const int* __restrict__ ent,
                                                   const float* __restrict__ w_rel,
                                                   const float* __restrict__ b_rel,
                                                   float* __restrict__ pair_out) {
    __shared__ int s_res[NRES];
    __shared__ int s_sym[NRES];
    __shared__ int s_asym[NRES];
    __shared__ float s_base[CZ];

    int tid = threadIdx.x;
    int i = blockIdx.x;

    for (int t = tid; t < NRES; t += 256) {
        s_res[t]  = res[t];
        s_sym[t]  = sym[t];
        s_asym[t] = asym[t];
    }
    if (tid < CZ) s_base[tid] = b_rel[tid] + g_tfi[i * CZ + tid];
    __syncthreads();

    int cq = tid & 31;
    int jl = tid >> 5;

    int res_i  = s_res[i];
    int sym_i  = s_sym[i];
    int asym_i = s_asym[i];
    int ent_i  = ent[i];

    float4 base4 = ((const float4*)s_base)[cq];
    const float4* W4 = (const float4*)w_rel;
    float4 w66 = W4[66 * 32 + cq];

    int jstart = blockIdx.y * 192;
#pragma unroll 4
    for (int it = 0; it < 24; it++) {
        int j = jstart + it * 8 + jl;
        int rj = s_res[j], sj = s_sym[j], aj = s_asym[j];

        int off = res_i - rj + 32;
        off = min(max(off, 0), 64);
        int pos = (asym_i == aj) ? off : 65;

        int ed = ent_i - sj;
        float entf = (float)ed;

        int cc = sym_i - sj + 2;
        cc = min(max(cc, 0), 4);
        int chain = (ed != 0) ? cc : 5;

        float4 wp = W4[pos * 32 + cq];
        float4 wc = W4[(67 + chain) * 32 + cq];
        float4 tj = ((const float4*)(g_tfj + j * CZ))[cq];

        float4 o;
        o.x = base4.x + wp.x + entf * w66.x + wc.x + tj.x;
        o.y = base4.y + wp.y + entf * w66.y + wc.y + tj.y;
        o.z = base4.z + wp.z + entf * w66.z + wc.z + tj.z;
        o.w = base4.w + wp.w + entf * w66.w + wc.w + tj.w;

        ((float4*)(pair_out + ((size_t)i * NRES + j) * CZ))[cq] = o;
    }
}

// ---------------- launch ----------------
extern "C" void kernel_launch(void* const* d_in, const int* in_sizes, int n_in,
                              void* d_out, int out_size) {
    const float* tf     = (const float*)d_in[0];
    const float* msa    = (const float*)d_in[1];
    const int*   res    = (const int*)d_in[2];
    const int*   sym    = (const int*)d_in[3];
    const int*   asym   = (const int*)d_in[4];
    const int*   ent    = (const int*)d_in[5];
    const float* w_zi   = (const float*)d_in[6];
    const float* b_zi   = (const float*)d_in[7];
    const float* w_zj   = (const float*)d_in[8];
    const float* b_zj   = (const float*)d_in[9];
    const float* w_m    = (const float*)d_in[10];
    const float* b_m    = (const float*)d_in[11];
    const float* w_msa  = (const float*)d_in[12];
    const float* b_msa  = (const float*)d_in[13];
    const float* w_rel  = (const float*)d_in[14];
    const float* b_rel  = (const float*)d_in[15];

    float* msa_out  = (float*)d_out;
    float* pair_out = (float*)d_out + MSA_OUT_ELEMS;

    cudaFuncSetAttribute(msa_persist_kernel, cudaFuncAttributeMaxDynamicSharedMemorySize,
                         MSA_SMEM);

    wconv_kernel<<<49, 256>>>(w_msa);
    pre_kernel<<<NRES, 256>>>(tf, w_zi, b_zi, w_zj, b_zj, w_m, b_m, b_msa);
    msa_persist_kernel<<<GRID_MSA, 512, MSA_SMEM>>>(msa, msa_out);
    pair_kernel<<<dim3(NRES, 4), 256>>>(res, sym, asym, ent, w_rel, b_rel, pair_out);
}

// round 6
// speedup vs baseline: 1.8112x; 1.1424x over previous
#include <cuda_runtime.h>
#include <cuda_fp16.h>
#include <cstdint>

// Problem constants
#define NRES 768
#define TF   21
#define MSADIM 49
#define CZ   128
#define CM   256
#define MSA_OUT_ELEMS (512u*768u*256u)   // 100663296
#define M_TILES 6144                     // 393216 rows / 64
#define P_TILES 3072                     // 768 i * 4 j-chunks
#define TOT_ITEMS 9216
#define GRID_U 296                       // 2 CTAs per SM

// ---------------- device scratch ----------------
__device__ float  g_tfi[NRES * CZ];
__device__ float  g_tfj[NRES * CZ];
__device__ float  g_comb[NRES * CM];
__device__ __half g_wh[48 * CM];         // fp16 weights k=0..47
__device__ float  g_w48[CM];             // fp32 weight row k=48

// ---------------- smem layout per CTA (bytes) ----------------
// A_hi [64][56h]  stride 112   @ 0       (7168)
// A_lo                         @ 7168    (7168)
// W    [48][264h] stride 528   @ 14336   (25344)
// raw0 64x49 f32               @ 39680   (12544)
// raw1                         @ 52224   (12544)  -> 64768 total
#define A_STRIDE 112
#define W_STRIDE 528
#define OFF_ALO  7168
#define OFF_W    14336
#define OFF_RAW0 39680
#define OFF_RAW1 52224
#define U_SMEM   64768

// ---------------- helpers ----------------
__device__ __forceinline__ uint32_t smem_u32(const void* p) {
    uint32_t a;
    asm("{ .reg .u64 t; cvta.to.shared.u64 t, %1; cvt.u32.u64 %0, t; }" : "=r"(a) : "l"(p));
    return a;
}
__device__ __forceinline__ void cp16(uint32_t dst, const void* src) {
    asm volatile("cp.async.cg.shared.global [%0], [%1], 16;" :: "r"(dst), "l"(src) : "memory");
}
__device__ __forceinline__ void cp_commit() {
    asm volatile("cp.async.commit_group;" ::: "memory");
}
__device__ __forceinline__ void cp_wait_all() {
    asm volatile("cp.async.wait_group 0;" ::: "memory");
}

#define LDSM_X4(r, addr) \
    asm volatile("ldmatrix.sync.aligned.m8n8.x4.shared.b16 {%0,%1,%2,%3}, [%4];" \
                 : "=r"((r)[0]), "=r"((r)[1]), "=r"((r)[2]), "=r"((r)[3]) : "r"(addr))
#define LDSM_X4T(r, addr) \
    asm volatile("ldmatrix.sync.aligned.m8n8.x4.trans.shared.b16 {%0,%1,%2,%3}, [%4];" \
                 : "=r"((r)[0]), "=r"((r)[1]), "=r"((r)[2]), "=r"((r)[3]) : "r"(addr))
#define MMAF16(d, a, b0v, b1v) \
    asm volatile("mma.sync.aligned.m16n8k16.row.col.f32.f16.f16.f32 " \
                 "{%0,%1,%2,%3}, {%4,%5,%6,%7}, {%8,%9}, {%0,%1,%2,%3};" \
                 : "+f"((d)[0]), "+f"((d)[1]), "+f"((d)[2]), "+f"((d)[3]) \
                 : "r"((a)[0]), "r"((a)[1]), "r"((a)[2]), "r"((a)[3]), \
                   "r"(b0v), "r"(b1v))

// ---------------- kernel 1: precompute (pre + wconv merged) ----------------
__global__ void pre_kernel(const float* __restrict__ tf,
                           const float* __restrict__ wzi, const float* __restrict__ bzi,
                           const float* __restrict__ wzj, const float* __restrict__ bzj,
                           const float* __restrict__ wm,  const float* __restrict__ bm,
                           const float* __restrict__ bmsa, const float* __restrict__ wmsa) {
    int c = threadIdx.x;
    if (blockIdx.x >= NRES) {
        int k = blockIdx.x - NRES;   // 0..48
        float v = wmsa[k * CM + c];
        if (k < 48) g_wh[k * CM + c] = __float2half_rn(v);
        else        g_w48[c] = v;
        return;
    }
    __shared__ float t[TF];
    int i = blockIdx.x;
    if (c < TF) t[c] = tf[i * TF + c];
    __syncthreads();

    float am = bm[c] + bmsa[c];
#pragma unroll
    for (int k = 0; k < TF; k++) am += t[k] * wm[k * CM + c];
    g_comb[i * CM + c] = am;

    if (c < CZ) {
        float ai = bzi[c];
        float aj = bzj[c];
#pragma unroll
        for (int k = 0; k < TF; k++) {
            float tv = t[k];
            ai += tv * wzi[k * CZ + c];
            aj += tv * wzj[k * CZ + c];
        }
        g_tfi[i * CZ + c] = ai;
        g_tfj[i * CZ + c] = aj;
    }
}

// ---------------- kernel 2: unified persistent msa + pair ----------------
// Work items w = 0..9215, strided by 296 per CTA.
//   w%3 != 2 -> msa tile  idx = (w/3)*2 + (w%3)   (64 rows x 256 ch)
//   w%3 == 2 -> pair tile idx = w/3               (i = idx>>2, jchunk = idx&3)
__global__ void __launch_bounds__(256, 2) uni_kernel(const float* __restrict__ msa,
                                                     const int* __restrict__ res,
                                                     const int* __restrict__ sym,
                                                     const int* __restrict__ asym,
                                                     const int* __restrict__ ent,
                                                     const float* __restrict__ w_rel,
                                                     const float* __restrict__ b_rel,
                                                     float* __restrict__ out) {
    extern __shared__ char smem[];
    uint32_t sb = smem_u32(smem);
    int tid = threadIdx.x;
    int lane = tid & 31;
    int bid = blockIdx.x;
    float* msa_out  = out;
    float* pair_out = out + MSA_OUT_ELEMS;

    // stage weights once
    for (int g = tid; g < 1536; g += 256) {
        int row = g >> 5;
        int c = g & 31;
        cp16(sb + OFF_W + row * W_STRIDE + c * 16, (const char*)g_wh + row * 512 + c * 16);
    }
    // prefetch first msa tile raw
    {
        int wf = bid;
        while (wf < TOT_ITEMS && (wf % 3) == 2) wf += GRID_U;
        if (wf < TOT_ITEMS) {
            int m = (wf / 3) * 2 + (wf % 3);
            const char* src = (const char*)msa + (long)m * 12544;
            for (int g = tid; g < 784; g += 256)
                cp16(sb + OFF_RAW0 + g * 16, src + g * 16);
        }
    }
    cp_commit();

    int warp_m = (tid >> 5) & 1;   // 2 m-warps of 32 rows
    int warp_n = tid >> 6;         // 4 n-warps of 64 channels
    uint32_t aoff = (uint32_t)((warp_m * 32 + (lane & 15)) * A_STRIDE + (lane >> 4) * 16);
    uint32_t boff = (uint32_t)(((lane & 7) + ((lane >> 3) & 1) * 8) * W_STRIDE +
                               (warp_n * 64 + (lane >> 4) * 8) * 2);
    uint32_t b_base = sb + OFF_W + boff;
    int qr = lane >> 2;
    int qc = (lane & 3) * 2;
    int msa_cnt = 0;

    for (int w = bid; w < TOT_ITEMS; w += GRID_U) {
        if ((w % 3) != 2) {
            // ================= msa tile =================
            int t = (w / 3) * 2 + (w % 3);
            uint32_t raw_cur = (msa_cnt & 1) ? OFF_RAW1 : OFF_RAW0;
            uint32_t raw_nxt = (msa_cnt & 1) ? OFF_RAW0 : OFF_RAW1;
            msa_cnt++;
            const float* rawf = (const float*)(smem + raw_cur);

            cp_wait_all();
            __syncthreads();   // raw ready; prev tile done

            // convert raw -> A hi/lo fp16 (k<48)
            for (int g = tid; g < 1536; g += 256) {
                int row = g / 24;
                int p = g - row * 24;
                float a0 = rawf[row * 49 + 2 * p];
                float a1 = rawf[row * 49 + 2 * p + 1];
                __half h0 = __float2half_rn(a0);
                __half h1 = __float2half_rn(a1);
                __half l0 = __float2half_rn(a0 - __half2float(h0));
                __half l1 = __float2half_rn(a1 - __half2float(h1));
                uint32_t o = row * A_STRIDE + p * 4;
                *(__half2*)(smem + o)           = __halves2half2(h0, h1);
                *(__half2*)(smem + OFF_ALO + o) = __halves2half2(l0, l1);
            }
            __syncthreads();   // A ready

            // prefetch next msa tile's raw (overlaps MMA)
            {
                int wn = w + GRID_U;
                while (wn < TOT_ITEMS && (wn % 3) == 2) wn += GRID_U;
                if (wn < TOT_ITEMS) {
                    int m2 = (wn / 3) * 2 + (wn % 3);
                    const char* src = (const char*)msa + (long)m2 * 12544;
                    for (int g = tid; g < 784; g += 256)
                        cp16(sb + raw_nxt + g * 16, src + g * 16);
                }
            }
            cp_commit();

            // MMA: 3 k-steps, 2 terms
            float d[2][8][4];
#pragma unroll
            for (int mt = 0; mt < 2; mt++)
#pragma unroll
                for (int nt = 0; nt < 8; nt++)
#pragma unroll
                    for (int i = 0; i < 4; i++) d[mt][nt][i] = 0.0f;

#pragma unroll
            for (int ks = 0; ks < 3; ks++) {
                uint32_t ak = ks * 32;
                uint32_t bk = ks * 16 * W_STRIDE;

                uint32_t ah[2][4], al[2][4];
                LDSM_X4(ah[0], sb + aoff + ak);
                LDSM_X4(ah[1], sb + aoff + 16 * A_STRIDE + ak);
                LDSM_X4(al[0], sb + OFF_ALO + aoff + ak);
                LDSM_X4(al[1], sb + OFF_ALO + aoff + 16 * A_STRIDE + ak);

                uint32_t bh[4][4];
#pragma unroll
                for (int g = 0; g < 4; g++) LDSM_X4T(bh[g], b_base + bk + g * 32);

#pragma unroll
                for (int mt = 0; mt < 2; mt++)
#pragma unroll
                    for (int nt = 0; nt < 8; nt++) {
                        uint32_t b0v = bh[nt >> 1][(nt & 1) * 2];
                        uint32_t b1v = bh[nt >> 1][(nt & 1) * 2 + 1];
                        MMAF16(d[mt][nt], ah[mt], b0v, b1v);
                        MMAF16(d[mt][nt], al[mt], b0v, b1v);
                    }
            }

            // epilogue: + a48*w48 + comb, store
            long rowbase = (long)t * 64;
            int n0 = (int)(rowbase % NRES);
#pragma unroll
            for (int mt = 0; mt < 2; mt++) {
                int lrow0 = warp_m * 32 + mt * 16 + qr;
                float a48_0 = rawf[lrow0 * 49 + 48];
                float a48_1 = rawf[(lrow0 + 8) * 49 + 48];
#pragma unroll
                for (int nt = 0; nt < 8; nt++) {
                    int ch = warp_n * 64 + nt * 8 + qc;
                    float2 w48 = *(const float2*)(g_w48 + ch);
                    float2 cb0 = *(const float2*)(g_comb + (n0 + lrow0) * CM + ch);
                    float2 cb1 = *(const float2*)(g_comb + (n0 + lrow0 + 8) * CM + ch);
                    float2 o0 = make_float2(d[mt][nt][0] + a48_0 * w48.x + cb0.x,
                                            d[mt][nt][1] + a48_0 * w48.y + cb0.y);
                    float2 o1 = make_float2(d[mt][nt][2] + a48_1 * w48.x + cb1.x,
                                            d[mt][nt][3] + a48_1 * w48.y + cb1.y);
                    *(float2*)(msa_out + (rowbase + lrow0) * (long)CM + ch) = o0;
                    *(float2*)(msa_out + (rowbase + lrow0 + 8) * (long)CM + ch) = o1;
                }
            }
            __syncthreads();   // rawf/A reads done before next tile reuses them
        } else {
            // ================= pair tile =================
            int p = w / 3;
            int i = p >> 2;
            int jstart = (p & 3) * 192;
            int jl = tid >> 5;   // 8 j-lanes

            int res_i  = __ldg(res + i);
            int sym_i  = __ldg(sym + i);
            int asym_i = __ldg(asym + i);
            int ent_i  = __ldg(ent + i);

            float4 b4 = ((const float4*)b_rel)[lane];
            float4 ti = ((const float4*)(g_tfi + i * CZ))[lane];
            float4 base4 = make_float4(b4.x + ti.x, b4.y + ti.y, b4.z + ti.z, b4.w + ti.w);
            const float4* W4 = (const float4*)w_rel;
            float4 w66 = W4[66 * 32 + lane];

#pragma unroll 4
            for (int it = 0; it < 24; it++) {
                int j = jstart + it * 8 + jl;
                int rj = __ldg(res + j), sj = __ldg(sym + j), aj = __ldg(asym + j);

                int off = res_i - rj + 32;
                off = min(max(off, 0), 64);
                int pos = (asym_i == aj) ? off : 65;

                int ed = ent_i - sj;
                float entf = (float)ed;

                int cc = sym_i - sj + 2;
                cc = min(max(cc, 0), 4);
                int chain = (ed != 0) ? cc : 5;

                float4 wp = W4[pos * 32 + lane];
                float4 wc = W4[(67 + chain) * 32 + lane];
                float4 tj = ((const float4*)(g_tfj + j * CZ))[lane];

                float4 o;
                o.x = base4.x + wp.x + entf * w66.x + wc.x + tj.x;
                o.y = base4.y + wp.y + entf * w66.y + wc.y + tj.y;
                o.z = base4.z + wp.z + entf * w66.z + wc.z + tj.z;
                o.w = base4.w + wp.w + entf * w66.w + wc.w + tj.w;

                ((float4*)(pair_out + ((size_t)i * NRES + j) * CZ))[lane] = o;
            }
        }
    }
}

// ---------------- launch ----------------
extern "C" void kernel_launch(void* const* d_in, const int* in_sizes, int n_in,
                              void* d_out, int out_size) {
    const float* tf     = (const float*)d_in[0];
    const float* msa    = (const float*)d_in[1];
    const int*   res    = (const int*)d_in[2];
    const int*   sym    = (const int*)d_in[3];
    const int*   asym   = (const int*)d_in[4];
    const int*   ent    = (const int*)d_in[5];
    const float* w_zi   = (const float*)d_in[6];
    const float* b_zi   = (const float*)d_in[7];
    const float* w_zj   = (const float*)d_in[8];
    const float* b_zj   = (const float*)d_in[9];
    const float* w_m    = (const float*)d_in[10];
    const float* b_m    = (const float*)d_in[11];
    const float* w_msa  = (const float*)d_in[12];
    const float* b_msa  = (const float*)d_in[13];
    const float* w_rel  = (const float*)d_in[14];
    const float* b_rel  = (const float*)d_in[15];

    cudaFuncSetAttribute(uni_kernel, cudaFuncAttributeMaxDynamicSharedMemorySize, U_SMEM);

    pre_kernel<<<NRES + 49, 256>>>(tf, w_zi, b_zi, w_zj, b_zj, w_m, b_m, b_msa, w_msa);
    uni_kernel<<<GRID_U, 256, U_SMEM>>>(msa, res, sym, asym, ent, w_rel, b_rel,
                                        (float*)d_out);
}

// round 7
// speedup vs baseline: 1.8228x; 1.0064x over previous
#include <cuda_runtime.h>
#include <cuda_fp16.h>
#include <cstdint>

// Problem constants
#define NRES 768
#define TF   21
#define MSADIM 49
#define CZ   128
#define CM   256
#define MSA_OUT_ELEMS (512u*768u*256u)   // 100663296
#define M_TILES 12288                    // 393216 rows / 32
#define P_TILES 3072
#define TOT_ITEMS 15360                  // 5 * 3072
#define GRID_U 444                       // 3 CTAs per SM

// ---------------- device scratch ----------------
__device__ float  g_tfi[NRES * CZ];
__device__ float  g_tfj[NRES * CZ];
__device__ float  g_comb[NRES * CM];
__device__ __half g_wh[48 * CM];         // fp16 weights k=0..47
__device__ float  g_w48[CM];             // fp32 weight row k=48

// ---------------- smem layout per CTA (bytes) ----------------
// A_hi [32][56h]  stride 112   @ 0       (3584)
// A_lo                         @ 3584    (3584)
// W    [48][264h] stride 528   @ 7168    (25344)
// raw0 32x49 f32               @ 32512   (6272)
// raw1                         @ 38784   (6272)  -> 45056 total
#define A_STRIDE 112
#define W_STRIDE 528
#define OFF_ALO  3584
#define OFF_W    7168
#define OFF_RAW0 32512
#define OFF_RAW1 38784
#define U_SMEM   45056

// ---------------- helpers ----------------
__device__ __forceinline__ uint32_t smem_u32(const void* p) {
    uint32_t a;
    asm("{ .reg .u64 t; cvta.to.shared.u64 t, %1; cvt.u32.u64 %0, t; }" : "=r"(a) : "l"(p));
    return a;
}
__device__ __forceinline__ void cp16(uint32_t dst, const void* src) {
    asm volatile("cp.async.cg.shared.global [%0], [%1], 16;" :: "r"(dst), "l"(src) : "memory");
}
__device__ __forceinline__ void cp_commit() {
    asm volatile("cp.async.commit_group;" ::: "memory");
}
__device__ __forceinline__ void cp_wait_all() {
    asm volatile("cp.async.wait_group 0;" ::: "memory");
}

#define LDSM_X4(r, addr) \
    asm volatile("ldmatrix.sync.aligned.m8n8.x4.shared.b16 {%0,%1,%2,%3}, [%4];" \
                 : "=r"((r)[0]), "=r"((r)[1]), "=r"((r)[2]), "=r"((r)[3]) : "r"(addr))
#define LDSM_X4T(r, addr) \
    asm volatile("ldmatrix.sync.aligned.m8n8.x4.trans.shared.b16 {%0,%1,%2,%3}, [%4];" \
                 : "=r"((r)[0]), "=r"((r)[1]), "=r"((r)[2]), "=r"((r)[3]) : "r"(addr))
#define MMAF16(d, a, b0v, b1v) \
    asm volatile("mma.sync.aligned.m16n8k16.row.col.f32.f16.f16.f32 " \
                 "{%0,%1,%2,%3}, {%4,%5,%6,%7}, {%8,%9}, {%0,%1,%2,%3};" \
                 : "+f"((d)[0]), "+f"((d)[1]), "+f"((d)[2]), "+f"((d)[3]) \
                 : "r"((a)[0]), "r"((a)[1]), "r"((a)[2]), "r"((a)[3]), \
                   "r"(b0v), "r"(b1v))

// ---------------- kernel 1: precompute ----------------
// blocks 0..95: 8 residues each, weights staged in smem. blocks 96..144: wconv.
__global__ void __launch_bounds__(256) pre_kernel(
        const float* __restrict__ tf,
        const float* __restrict__ wzi, const float* __restrict__ bzi,
        const float* __restrict__ wzj, const float* __restrict__ bzj,
        const float* __restrict__ wm,  const float* __restrict__ bm,
        const float* __restrict__ bmsa, const float* __restrict__ wmsa) {
    int c = threadIdx.x;
    if (blockIdx.x >= 96) {
        int k = blockIdx.x - 96;   // 0..48
        float v = wmsa[k * CM + c];
        if (k < 48) g_wh[k * CM + c] = __float2half_rn(v);
        else        g_w48[c] = v;
        return;
    }
    __shared__ float swm[TF * CM];       // 21504 B
    __shared__ float swi[TF * CZ];       // 10752 B
    __shared__ float swj[TF * CZ];       // 10752 B
    __shared__ float st[8 * TF];

    for (int g = c; g < TF * CM; g += 256) swm[g] = wm[g];
    for (int g = c; g < TF * CZ; g += 256) { swi[g] = wzi[g]; swj[g] = wzj[g]; }
    int i0 = blockIdx.x * 8;
    for (int g = c; g < 8 * TF; g += 256) st[g] = tf[i0 * TF + g];
    __syncthreads();

    float bmv = bm[c] + bmsa[c];
    float bzi_v = (c < CZ) ? bzi[c] : 0.0f;
    float bzj_v = (c < CZ) ? bzj[c] : 0.0f;

#pragma unroll 1
    for (int r = 0; r < 8; r++) {
        const float* t = st + r * TF;
        float am = bmv;
#pragma unroll
        for (int k = 0; k < TF; k++) am += t[k] * swm[k * CM + c];
        g_comb[(i0 + r) * CM + c] = am;

        if (c < CZ) {
            float ai = bzi_v;
            float aj = bzj_v;
#pragma unroll
            for (int k = 0; k < TF; k++) {
                float tv = t[k];
                ai += tv * swi[k * CZ + c];
                aj += tv * swj[k * CZ + c];
            }
            g_tfi[(i0 + r) * CZ + c] = ai;
            g_tfj[(i0 + r) * CZ + c] = aj;
        }
    }
}

// ---------------- kernel 2: unified persistent msa + pair ----------------
// Items w = 0..15359 strided by 444.
//   w%5 != 4 -> msa tile  t = (w/5)*4 + (w%5)   (32 rows x 256 ch)
//   w%5 == 4 -> pair tile p = w/5               (i = p>>2, jchunk = p&3)
__global__ void __launch_bounds__(256, 3) uni_kernel(const float* __restrict__ msa,
                                                     const int* __restrict__ res,
                                                     const int* __restrict__ sym,
                                                     const int* __restrict__ asym,
                                                     const int* __restrict__ ent,
                                                     const float* __restrict__ w_rel,
                                                     const float* __restrict__ b_rel,
                                                     float* __restrict__ out) {
    extern __shared__ char smem[];
    uint32_t sb = smem_u32(smem);
    int tid = threadIdx.x;
    int lane = tid & 31;
    int bid = blockIdx.x;
    float* msa_out  = out;
    float* pair_out = out + MSA_OUT_ELEMS;

    // stage weights once
    for (int g = tid; g < 1536; g += 256) {
        int row = g >> 5;
        int c = g & 31;
        cp16(sb + OFF_W + row * W_STRIDE + c * 16, (const char*)g_wh + row * 512 + c * 16);
    }
    // prefetch first msa tile raw
    {
        int wf = bid;
        while (wf < TOT_ITEMS && (wf % 5) == 4) wf += GRID_U;
        if (wf < TOT_ITEMS) {
            int m = (wf / 5) * 4 + (wf % 5);
            const char* src = (const char*)msa + (long)m * 6272;
            for (int g = tid; g < 392; g += 256)
                cp16(sb + OFF_RAW0 + g * 16, src + g * 16);
        }
    }
    cp_commit();

    int wid = tid >> 5;
    int warp_m = wid & 1;          // 2 m-warps of 16 rows
    int warp_n = wid >> 1;         // 4 n-warps of 64 channels
    uint32_t aoff = (uint32_t)((warp_m * 16 + (lane & 15)) * A_STRIDE + (lane >> 4) * 16);
    uint32_t boff = (uint32_t)(((lane & 7) + ((lane >> 3) & 1) * 8) * W_STRIDE +
                               (warp_n * 64 + (lane >> 4) * 8) * 2);
    uint32_t b_base = sb + OFF_W + boff;
    int qr = lane >> 2;
    int qc = (lane & 3) * 2;
    int msa_cnt = 0;

    for (int w = bid; w < TOT_ITEMS; w += GRID_U) {
        if ((w % 5) != 4) {
            // ================= msa tile (32 rows) =================
            int t = (w / 5) * 4 + (w % 5);
            uint32_t raw_cur = (msa_cnt & 1) ? OFF_RAW1 : OFF_RAW0;
            uint32_t raw_nxt = (msa_cnt & 1) ? OFF_RAW0 : OFF_RAW1;
            msa_cnt++;
            const float* rawf = (const float*)(smem + raw_cur);

            cp_wait_all();
            __syncthreads();   // raw ready; prev tile done

            // convert raw -> A hi/lo fp16 (k<48): 32 rows x 24 float-pairs
            for (int g = tid; g < 768; g += 256) {
                int row = g / 24;
                int p = g - row * 24;
                float a0 = rawf[row * 49 + 2 * p];
                float a1 = rawf[row * 49 + 2 * p + 1];
                __half h0 = __float2half_rn(a0);
                __half h1 = __float2half_rn(a1);
                __half l0 = __float2half_rn(a0 - __half2float(h0));
                __half l1 = __float2half_rn(a1 - __half2float(h1));
                uint32_t o = row * A_STRIDE + p * 4;
                *(__half2*)(smem + o)           = __halves2half2(h0, h1);
                *(__half2*)(smem + OFF_ALO + o) = __halves2half2(l0, l1);
            }
            __syncthreads();   // A ready

            // prefetch next msa tile's raw (overlaps MMA)
            {
                int wn = w + GRID_U;
                while (wn < TOT_ITEMS && (wn % 5) == 4) wn += GRID_U;
                if (wn < TOT_ITEMS) {
                    int m2 = (wn / 5) * 4 + (wn % 5);
                    const char* src = (const char*)msa + (long)m2 * 6272;
                    for (int g = tid; g < 392; g += 256)
                        cp16(sb + raw_nxt + g * 16, src + g * 16);
                }
            }
            cp_commit();

            // MMA: 3 k-steps, 2 terms, warp = m16 x n64
            float d[8][4];
#pragma unroll
            for (int nt = 0; nt < 8; nt++)
#pragma unroll
                for (int i = 0; i < 4; i++) d[nt][i] = 0.0f;

#pragma unroll
            for (int ks = 0; ks < 3; ks++) {
                uint32_t ak = ks * 32;
                uint32_t bk = ks * 16 * W_STRIDE;

                uint32_t ah[4], al[4];
                LDSM_X4(ah, sb + aoff + ak);
                LDSM_X4(al, sb + OFF_ALO + aoff + ak);

                uint32_t bh[4][4];
#pragma unroll
                for (int g = 0; g < 4; g++) LDSM_X4T(bh[g], b_base + bk + g * 32);

#pragma unroll
                for (int nt = 0; nt < 8; nt++) {
                    uint32_t b0v = bh[nt >> 1][(nt & 1) * 2];
                    uint32_t b1v = bh[nt >> 1][(nt & 1) * 2 + 1];
                    MMAF16(d[nt], ah, b0v, b1v);
                    MMAF16(d[nt], al, b0v, b1v);
                }
            }

            // epilogue: + a48*w48 + comb, store
            long rowbase = (long)t * 32;
            int n0 = (int)(rowbase % NRES);
            int lrow0 = warp_m * 16 + qr;
            float a48_0 = rawf[lrow0 * 49 + 48];
            float a48_1 = rawf[(lrow0 + 8) * 49 + 48];
#pragma unroll
            for (int nt = 0; nt < 8; nt++) {
                int ch = warp_n * 64 + nt * 8 + qc;
                float2 w48 = *(const float2*)(g_w48 + ch);
                float2 cb0 = *(const float2*)(g_comb + (n0 + lrow0) * CM + ch);
                float2 cb1 = *(const float2*)(g_comb + (n0 + lrow0 + 8) * CM + ch);
                float2 o0 = make_float2(d[nt][0] + a48_0 * w48.x + cb0.x,
                                        d[nt][1] + a48_0 * w48.y + cb0.y);
                float2 o1 = make_float2(d[nt][2] + a48_1 * w48.x + cb1.x,
                                        d[nt][3] + a48_1 * w48.y + cb1.y);
                *(float2*)(msa_out + (rowbase + lrow0) * (long)CM + ch) = o0;
                *(float2*)(msa_out + (rowbase + lrow0 + 8) * (long)CM + ch) = o1;
            }
            __syncthreads();   // rawf/A reads done before next tile reuses buffers
        } else {
            // ================= pair tile =================
            int p = w / 5;
            int i = p >> 2;
            int jstart = (p & 3) * 192;
            int jl = tid >> 5;   // 8 j-lanes

            int res_i  = __ldg(res + i);
            int sym_i  = __ldg(sym + i);
            int asym_i = __ldg(asym + i);
            int ent_i  = __ldg(ent + i);

            float4 b4 = ((const float4*)b_rel)[lane];
            float4 ti = ((const float4*)(g_tfi + i * CZ))[lane];
            float4 base4 = make_float4(b4.x + ti.x, b4.y + ti.y, b4.z + ti.z, b4.w + ti.w);
            const float4* W4 = (const float4*)w_rel;
            float4 w66 = W4[66 * 32 + lane];

#pragma unroll 4
            for (int it = 0; it < 24; it++) {
                int j = jstart + it * 8 + jl;
                int rj = __ldg(res + j), sj = __ldg(sym + j), aj = __ldg(asym + j);

                int off = res_i - rj + 32;
                off = min(max(off, 0), 64);
                int pos = (asym_i == aj) ? off : 65;

                int ed = ent_i - sj;
                float entf = (float)ed;

                int cc = sym_i - sj + 2;
                cc = min(max(cc, 0), 4);
                int chain = (ed != 0) ? cc : 5;

                float4 wp = W4[pos * 32 + lane];
                float4 wc = W4[(67 + chain) * 32 + lane];
                float4 tj = ((const float4*)(g_tfj + j * CZ))[lane];

                float4 o;
                o.x = base4.x + wp.x + entf * w66.x + wc.x + tj.x;
                o.y = base4.y + wp.y + entf * w66.y + wc.y + tj.y;
                o.z = base4.z + wp.z + entf * w66.z + wc.z + tj.z;
                o.w = base4.w + wp.w + entf * w66.w + wc.w + tj.w;

                ((float4*)(pair_out + ((size_t)i * NRES + j) * CZ))[lane] = o;
            }
        }
    }
}

// ---------------- launch ----------------
extern "C" void kernel_launch(void* const* d_in, const int* in_sizes, int n_in,
                              void* d_out, int out_size) {
    const float* tf     = (const float*)d_in[0];
    const float* msa    = (const float*)d_in[1];
    const int*   res    = (const int*)d_in[2];
    const int*   sym    = (const int*)d_in[3];
    const int*   asym   = (const int*)d_in[4];
    const int*   ent    = (const int*)d_in[5];
    const float* w_zi   = (const float*)d_in[6];
    const float* b_zi   = (const float*)d_in[7];
    const float* w_zj   = (const float*)d_in[8];
    const float* b_zj   = (const float*)d_in[9];
    const float* w_m    = (const float*)d_in[10];
    const float* b_m    = (const float*)d_in[11];
    const float* w_msa  = (const float*)d_in[12];
    const float* b_msa  = (const float*)d_in[13];
    const float* w_rel  = (const float*)d_in[14];
    const float* b_rel  = (const float*)d_in[15];

    cudaFuncSetAttribute(uni_kernel, cudaFuncAttributeMaxDynamicSharedMemorySize, U_SMEM);

    pre_kernel<<<96 + 49, 256>>>(tf, w_zi, b_zi, w_zj, b_zj, w_m, b_m, b_msa, w_msa);
    uni_kernel<<<GRID_U, 256, U_SMEM>>>(msa, res, sym, asym, ent, w_rel, b_rel,
                                        (float*)d_out);
}

// round 8
// speedup vs baseline: 2.2382x; 1.2279x over previous
#include <cuda_runtime.h>
#include <cuda_fp16.h>
#include <cstdint>

// Problem constants
#define NRES 768
#define TF   21
#define MSADIM 49
#define CZ   128
#define CM   256
#define MSA_OUT_ELEMS (512u*768u*256u)   // 100663296
#define TOT_ITEMS 15360                  // 5 * 3072
#define GRID_U 444                       // 3 CTAs per SM

// ---------------- device scratch ----------------
__device__ float  g_tfi[NRES * CZ];
__device__ float  g_tfj[NRES * CZ];
__device__ float  g_comb[NRES * CM];
__device__ __half g_wh[48 * CM];         // fp16 weights k=0..47
__device__ float  g_w48[CM];             // fp32 weight row k=48

// ---------------- smem layout per CTA (bytes) ----------------
#define A_STRIDE 112
#define W_STRIDE 528
#define OFF_ALO  3584
#define OFF_W    7168
#define OFF_RAW0 32512
#define OFF_RAW1 38784
#define OFF_W48  45056
#define OFF_A48  46080
#define OFF_STG  46208
#define STG_STRIDE 1056
#define U_SMEM   63488

// ---------------- helpers ----------------
__device__ __forceinline__ uint32_t smem_u32(const void* p) {
    uint32_t a;
    asm("{ .reg .u64 t; cvta.to.shared.u64 t, %1; cvt.u32.u64 %0, t; }" : "=r"(a) : "l"(p));
    return a;
}
__device__ __forceinline__ void cp16(uint32_t dst, const void* src) {
    asm volatile("cp.async.cg.shared.global [%0], [%1], 16;" :: "r"(dst), "l"(src) : "memory");
}
__device__ __forceinline__ void cp_commit() {
    asm volatile("cp.async.commit_group;" ::: "memory");
}
__device__ __forceinline__ void cp_wait_all() {
    asm volatile("cp.async.wait_group 0;" ::: "memory");
}

#define LDSM_X4(r, addr) \
    asm volatile("ldmatrix.sync.aligned.m8n8.x4.shared.b16 {%0,%1,%2,%3}, [%4];" \
                 : "=r"((r)[0]), "=r"((r)[1]), "=r"((r)[2]), "=r"((r)[3]) : "r"(addr))
#define LDSM_X4T(r, addr) \
    asm volatile("ldmatrix.sync.aligned.m8n8.x4.trans.shared.b16 {%0,%1,%2,%3}, [%4];" \
                 : "=r"((r)[0]), "=r"((r)[1]), "=r"((r)[2]), "=r"((r)[3]) : "r"(addr))
#define MMAF16(d, a, b0v, b1v) \
    asm volatile("mma.sync.aligned.m16n8k16.row.col.f32.f16.f16.f32 " \
                 "{%0,%1,%2,%3}, {%4,%5,%6,%7}, {%8,%9}, {%0,%1,%2,%3};" \
                 : "+f"((d)[0]), "+f"((d)[1]), "+f"((d)[2]), "+f"((d)[3]) \
                 : "r"((a)[0]), "r"((a)[1]), "r"((a)[2]), "r"((a)[3]), \
                   "r"(b0v), "r"(b1v))

// ---------------- kernel 1: precompute ----------------
__global__ void __launch_bounds__(256) pre_kernel(
        const float* __restrict__ tf,
        const float* __restrict__ wzi, const float* __restrict__ bzi,
        const float* __restrict__ wzj, const float* __restrict__ bzj,
        const float* __restrict__ wm,  const float* __restrict__ bm,
        const float* __restrict__ bmsa, const float* __restrict__ wmsa) {
    int c = threadIdx.x;
    if (blockIdx.x >= 96) {
        int k = blockIdx.x - 96;   // 0..48
        float v = wmsa[k * CM + c];
        if (k < 48) g_wh[k * CM + c] = __float2half_rn(v);
        else        g_w48[c] = v;
        return;
    }
    __shared__ float swm[TF * CM];
    __shared__ float swi[TF * CZ];
    __shared__ float swj[TF * CZ];
    __shared__ float st[8 * TF];

    for (int g = c; g < TF * CM; g += 256) swm[g] = wm[g];
    for (int g = c; g < TF * CZ; g += 256) { swi[g] = wzi[g]; swj[g] = wzj[g]; }
    int i0 = blockIdx.x * 8;
    for (int g = c; g < 8 * TF; g += 256) st[g] = tf[i0 * TF + g];
    __syncthreads();

    float bmv = bm[c] + bmsa[c];
    float bzi_v = (c < CZ) ? bzi[c] : 0.0f;
    float bzj_v = (c < CZ) ? bzj[c] : 0.0f;

#pragma unroll 1
    for (int r = 0; r < 8; r++) {
        const float* t = st + r * TF;
        float am = bmv;
#pragma unroll
        for (int k = 0; k < TF; k++) am += t[k] * swm[k * CM + c];
        g_comb[(i0 + r) * CM + c] = am;

        if (c < CZ) {
            float ai = bzi_v;
            float aj = bzj_v;
#pragma unroll
            for (int k = 0; k < TF; k++) {
                float tv = t[k];
                ai += tv * swi[k * CZ + c];
                aj += tv * swj[k * CZ + c];
            }
            g_tfi[(i0 + r) * CZ + c] = ai;
            g_tfj[(i0 + r) * CZ + c] = aj;
        }
    }
}

// ---------------- kernel 2: unified persistent msa + pair ----------------
__global__ void __launch_bounds__(256, 3) uni_kernel(const float* __restrict__ msa,
                                                     const int* __restrict__ res,
                                                     const int* __restrict__ sym,
                                                     const int* __restrict__ asym,
                                                     const int* __restrict__ ent,
                                                     const float* __restrict__ w_rel,
                                                     const float* __restrict__ b_rel,
                                                     float* __restrict__ out) {
    extern __shared__ char smem[];
    uint32_t sb = smem_u32(smem);
    int tid = threadIdx.x;
    int lane = tid & 31;
    int bid = blockIdx.x;
    float* msa_out  = out;
    float* pair_out = out + MSA_OUT_ELEMS;

    // stage weights + w48 once
    for (int g = tid; g < 1536; g += 256) {
        int row = g >> 5;
        int c = g & 31;
        cp16(sb + OFF_W + row * W_STRIDE + c * 16, (const char*)g_wh + row * 512 + c * 16);
    }
    if (tid < 64) cp16(sb + OFF_W48 + tid * 16, (const char*)g_w48 + tid * 16);
    // prefetch first msa tile raw
    {
        int wf = bid;
        while (wf < TOT_ITEMS && (wf % 5) == 4) wf += GRID_U;
        if (wf < TOT_ITEMS) {
            int m = (wf / 5) * 4 + (wf % 5);
            const char* src = (const char*)msa + (long)m * 6272;
            for (int g = tid; g < 392; g += 256)
                cp16(sb + OFF_RAW0 + g * 16, src + g * 16);
        }
    }
    cp_commit();

    int wid = tid >> 5;
    int warp_m = wid & 1;          // 2 m-warps of 16 rows
    int warp_n = wid >> 1;         // 4 n-warps of 64 channels
    uint32_t aoff = (uint32_t)((warp_m * 16 + (lane & 15)) * A_STRIDE + (lane >> 4) * 16);
    uint32_t boff = (uint32_t)(((lane & 7) + ((lane >> 3) & 1) * 8) * W_STRIDE +
                               (warp_n * 64 + (lane >> 4) * 8) * 2);
    uint32_t b_base = sb + OFF_W + boff;
    int qr = lane >> 2;
    int qc = (lane & 3) * 2;
    int msa_cnt = 0;

    const float* s_w48f = (const float*)(smem + OFF_W48);
    const float* s_a48f = (const float*)(smem + OFF_A48);

    for (int w = bid; w < TOT_ITEMS; w += GRID_U) {
        if ((w % 5) != 4) {
            // ================= msa tile (32 rows x 256 ch) =================
            int t = (w / 5) * 4 + (w % 5);
            uint32_t raw_cur = (msa_cnt & 1) ? OFF_RAW1 : OFF_RAW0;
            uint32_t raw_nxt = (msa_cnt & 1) ? OFF_RAW0 : OFF_RAW1;
            msa_cnt++;
            const float* rawf = (const float*)(smem + raw_cur);

            cp_wait_all();
            __syncthreads();   // raw ready; prev tile done

            // convert raw -> A hi/lo fp16 (k<48); also stash a48 column
            for (int g = tid; g < 768; g += 256) {
                int row = g / 24;
                int p = g - row * 24;
                float a0 = rawf[row * 49 + 2 * p];
                float a1 = rawf[row * 49 + 2 * p + 1];
                __half h0 = __float2half_rn(a0);
                __half h1 = __float2half_rn(a1);
                __half l0 = __float2half_rn(a0 - __half2float(h0));
                __half l1 = __float2half_rn(a1 - __half2float(h1));
                uint32_t o = row * A_STRIDE + p * 4;
                *(__half2*)(smem + o)           = __halves2half2(h0, h1);
                *(__half2*)(smem + OFF_ALO + o) = __halves2half2(l0, l1);
            }
            if (tid < 32) ((float*)(smem + OFF_A48))[tid] = rawf[tid * 49 + 48];
            __syncthreads();   // A ready

            // prefetch next msa tile's raw (overlaps MMA)
            {
                int wn = w + GRID_U;
                while (wn < TOT_ITEMS && (wn % 5) == 4) wn += GRID_U;
                if (wn < TOT_ITEMS) {
                    int m2 = (wn / 5) * 4 + (wn % 5);
                    const char* src = (const char*)msa + (long)m2 * 6272;
                    for (int g = tid; g < 392; g += 256)
                        cp16(sb + raw_nxt + g * 16, src + g * 16);
                }
            }
            cp_commit();

            // MMA: 3 k-steps, 2 terms, warp = m16 x n64
            float d[8][4];
#pragma unroll
            for (int nt = 0; nt < 8; nt++)
#pragma unroll
                for (int i = 0; i < 4; i++) d[nt][i] = 0.0f;

#pragma unroll
            for (int ks = 0; ks < 3; ks++) {
                uint32_t ak = ks * 32;
                uint32_t bk = ks * 16 * W_STRIDE;

                uint32_t ah[4], al[4];
                LDSM_X4(ah, sb + aoff + ak);
                LDSM_X4(al, sb + OFF_ALO + aoff + ak);

                uint32_t bh[4][4];
#pragma unroll
                for (int g = 0; g < 4; g++) LDSM_X4T(bh[g], b_base + bk + g * 32);

#pragma unroll
                for (int nt = 0; nt < 8; nt++) {
                    uint32_t b0v = bh[nt >> 1][(nt & 1) * 2];
                    uint32_t b1v = bh[nt >> 1][(nt & 1) * 2 + 1];
                    MMAF16(d[nt], ah, b0v, b1v);
                    MMAF16(d[nt], al, b0v, b1v);
                }
            }

            // ---- epilogue: smem-staged, coalesced loads+stores ----
            long rowbase = (long)t * 32;
            int n0 = (int)(rowbase % NRES);
#pragma unroll
            for (int half = 0; half < 2; half++) {
                if (warp_m == half) {
                    char* stg = smem + OFF_STG;
                    int chb = (warp_n * 64 + qc) * 4;
#pragma unroll
                    for (int nt = 0; nt < 8; nt++) {
                        *(float2*)(stg + qr * STG_STRIDE + chb + nt * 32) =
                            make_float2(d[nt][0], d[nt][1]);
                        *(float2*)(stg + (qr + 8) * STG_STRIDE + chb + nt * 32) =
                            make_float2(d[nt][2], d[nt][3]);
                    }
                }
                __syncthreads();
#pragma unroll
                for (int p = 0; p < 4; p++) {
                    int g = tid + p * 256;
                    int row = g >> 6;        // 0..15
                    int c4 = g & 63;
                    float4 v = *(const float4*)(smem + OFF_STG + row * STG_STRIDE + c4 * 16);
                    float4 w48v = *(const float4*)(s_w48f + c4 * 4);
                    float a48v = s_a48f[half * 16 + row];
                    int grow = half * 16 + row;
                    float4 cb = *(const float4*)(g_comb + (n0 + grow) * CM + c4 * 4);
                    float4 o = make_float4(v.x + a48v * w48v.x + cb.x,
                                           v.y + a48v * w48v.y + cb.y,
                                           v.z + a48v * w48v.z + cb.z,
                                           v.w + a48v * w48v.w + cb.w);
                    *(float4*)(msa_out + (rowbase + grow) * (long)CM + c4 * 4) = o;
                }
                __syncthreads();
            }
        } else {
            // ================= pair tile =================
            int p = w / 5;
            int i = p >> 2;
            int jstart = (p & 3) * 192;
            int jl = tid >> 5;   // 8 j-lanes

            int res_i  = __ldg(res + i);
            int sym_i  = __ldg(sym + i);
            int asym_i = __ldg(asym + i);
            int ent_i  = __ldg(ent + i);

            float4 b4 = ((const float4*)b_rel)[lane];
            float4 ti = ((const float4*)(g_tfi + i * CZ))[lane];
            float4 base4 = make_float4(b4.x + ti.x, b4.y + ti.y, b4.z + ti.z, b4.w + ti.w);
            const float4* W4 = (const float4*)w_rel;
            float4 w66 = W4[66 * 32 + lane];

#pragma unroll 4
            for (int it = 0; it < 24; it++) {
                int j = jstart + it * 8 + jl;
                int rj = __ldg(res + j), sj = __ldg(sym + j), aj = __ldg(asym + j);

                int off = res_i - rj + 32;
                off = min(max(off, 0), 64);
                int pos = (asym_i == aj) ? off : 65;

                int ed = ent_i - sj;
                float entf = (float)ed;

                int cc = sym_i - sj + 2;
                cc = min(max(cc, 0), 4);
                int chain = (ed != 0) ? cc : 5;

                float4 wp = W4[pos * 32 + lane];
                float4 wc = W4[(67 + chain) * 32 + lane];
                float4 tj = ((const float4*)(g_tfj + j * CZ))[lane];

                float4 o;
                o.x = base4.x + wp.x + entf * w66.x + wc.x + tj.x;
                o.y = base4.y + wp.y + entf * w66.y + wc.y + tj.y;
                o.z = base4.z + wp.z + entf * w66.z + wc.z + tj.z;
                o.w = base4.w + wp.w + entf * w66.w + wc.w + tj.w;

                ((float4*)(pair_out + ((size_t)i * NRES + j) * CZ))[lane] = o;
            }
        }
    }
}

// ---------------- launch ----------------
extern "C" void kernel_launch(void* const* d_in, const int* in_sizes, int n_in,
                              void* d_out, int out_size) {
    const float* tf     = (const float*)d_in[0];
    const float* msa    = (const float*)d_in[1];
    const int*   res    = (const int*)d_in[2];
    const int*   sym    = (const int*)d_in[3];
    const int*   asym   = (const int*)d_in[4];
    const int*   ent    = (const int*)d_in[5];
    const float* w_zi   = (const float*)d_in[6];
    const float* b_zi   = (const float*)d_in[7];
    const float* w_zj   = (const float*)d_in[8];
    const float* b_zj   = (const float*)d_in[9];
    const float* w_m    = (const float*)d_in[10];
    const float* b_m    = (const float*)d_in[11];
    const float* w_msa  = (const float*)d_in[12];
    const float* b_msa  = (const float*)d_in[13];
    const float* w_rel  = (const float*)d_in[14];
    const float* b_rel  = (const float*)d_in[15];

    cudaFuncSetAttribute(uni_kernel, cudaFuncAttributeMaxDynamicSharedMemorySize, U_SMEM);

    pre_kernel<<<96 + 49, 256>>>(tf, w_zi, b_zi, w_zj, b_zj, w_m, b_m, b_msa, w_msa);
    uni_kernel<<<GRID_U, 256, U_SMEM>>>(msa, res, sym, asym, ent, w_rel, b_rel,
                                        (float*)d_out);
}